// round 2
// baseline (speedup 1.0000x reference)
#include <cuda_runtime.h>

#define N_NODES 100000
#define F_IN 512
#define HID 16
#define CLS 7
#define HID2 8   // CLS padded to 8 for aligned vector atomics

// ---------------- device scratch (no allocs allowed) ----------------
__device__ __align__(16) float g_deg [N_NODES];
__device__ __align__(16) float g_dinv[N_NODES];
__device__ __align__(16) float g_h1  [N_NODES * HID];
__device__ __align__(16) float g_agg1[N_NODES * HID];
__device__ __align__(16) float g_h2  [N_NODES * HID2];
__device__ __align__(16) float g_agg2[N_NODES * HID2];
__device__ int g_is64;

// vector reduction: 4 floats in one L2 atomic op (sm_90+)
__device__ __forceinline__ void red_add_v4(float* p, float a, float b, float c, float d) {
    asm volatile("red.global.add.v4.f32 [%0], {%1, %2, %3, %4};"
                 :: "l"(p), "f"(a), "f"(b), "f"(c), "f"(d) : "memory");
}

// ---------------- dtype detection for edge_index ----------------
// If the buffer holds int64 values < 2^31, every odd 32-bit word is 0.
// If it holds int32 node indices, odd words are random indices in [0,1e5).
__global__ void k_detect(const unsigned int* __restrict__ w) {
    if (blockIdx.x == 0 && threadIdx.x == 0) {
        int all0 = 1;
        #pragma unroll 1
        for (int k = 0; k < 64; k++) {
            long idx = 2L * k * 50001L + 1L;   // stays < 6.4M words
            if (w[idx] != 0u) all0 = 0;
        }
        g_is64 = all0;
    }
}

// ---------------- init: zero accumulators, deg = 1 (self loop) ----------------
__global__ void k_init() {
    int tid = blockIdx.x * blockDim.x + threadIdx.x;
    int stride = gridDim.x * blockDim.x;
    for (int j = tid; j < N_NODES * HID;  j += stride) g_agg1[j] = 0.0f;
    for (int j = tid; j < N_NODES * HID2; j += stride) g_agg2[j] = 0.0f;
    for (int j = tid; j < N_NODES;        j += stride) g_deg[j]  = 1.0f;
}

// ---------------- degree count ----------------
__global__ void k_deg(const void* __restrict__ ei, int E) {
    int i = blockIdx.x * blockDim.x + threadIdx.x;
    if (i >= E) return;
    int dst;
    if (g_is64) dst = (int)((const long long*)ei)[(size_t)E + i];
    else        dst = ((const int*)ei)[(size_t)E + i];
    atomicAdd(&g_deg[dst], 1.0f);
}

__global__ void k_dinv() {
    int i = blockIdx.x * blockDim.x + threadIdx.x;
    if (i < N_NODES) g_dinv[i] = rsqrtf(g_deg[i]);   // deg >= 1 always
}

// ---------------- GEMM1: h1 = x @ W1   (100000 x 512 x 16) ----------------
__global__ void k_gemm1(const float* __restrict__ x, const float* __restrict__ W1) {
    __shared__ float Ws[F_IN * HID];            // 32 KB
    for (int i = threadIdx.x; i < F_IN * HID; i += blockDim.x) Ws[i] = W1[i];
    __syncthreads();

    int row = blockIdx.x * blockDim.x + threadIdx.x;
    if (row >= N_NODES) return;

    float acc[HID];
    #pragma unroll
    for (int j = 0; j < HID; j++) acc[j] = 0.0f;

    const float4* xr = reinterpret_cast<const float4*>(x + (size_t)row * F_IN);
    #pragma unroll 2
    for (int kq = 0; kq < F_IN / 4; kq++) {
        float4 xv = __ldg(&xr[kq]);
        const float* w = &Ws[kq * 4 * HID];
        #pragma unroll
        for (int j = 0; j < HID; j++) acc[j] = fmaf(xv.x, w[j],           acc[j]);
        #pragma unroll
        for (int j = 0; j < HID; j++) acc[j] = fmaf(xv.y, w[HID + j],     acc[j]);
        #pragma unroll
        for (int j = 0; j < HID; j++) acc[j] = fmaf(xv.z, w[2 * HID + j], acc[j]);
        #pragma unroll
        for (int j = 0; j < HID; j++) acc[j] = fmaf(xv.w, w[3 * HID + j], acc[j]);
    }

    float4* o = reinterpret_cast<float4*>(g_h1 + (size_t)row * HID);
    o[0] = make_float4(acc[0],  acc[1],  acc[2],  acc[3]);
    o[1] = make_float4(acc[4],  acc[5],  acc[6],  acc[7]);
    o[2] = make_float4(acc[8],  acc[9],  acc[10], acc[11]);
    o[3] = make_float4(acc[12], acc[13], acc[14], acc[15]);
}

// ---------------- edge scatter, layer 1 ----------------
__global__ void k_edge1(const void* __restrict__ ei, int E) {
    int i = blockIdx.x * blockDim.x + threadIdx.x;
    if (i >= E) return;
    int src, dst;
    if (g_is64) {
        const long long* e = (const long long*)ei;
        src = (int)__ldg(&e[i]); dst = (int)__ldg(&e[(size_t)E + i]);
    } else {
        const int* e = (const int*)ei;
        src = __ldg(&e[i]); dst = __ldg(&e[(size_t)E + i]);
    }
    float wgt = __ldg(&g_dinv[src]) * __ldg(&g_dinv[dst]);
    const float4* hs = reinterpret_cast<const float4*>(g_h1 + (size_t)src * HID);
    float* ad = g_agg1 + (size_t)dst * HID;
    #pragma unroll
    for (int q = 0; q < 4; q++) {
        float4 v = __ldg(&hs[q]);
        red_add_v4(ad + q * 4, v.x * wgt, v.y * wgt, v.z * wgt, v.w * wgt);
    }
}

// ---------------- finalize1: add self loop + bias, relu ----------------
__global__ void k_fin1(const float* __restrict__ b1) {
    int i = blockIdx.x * blockDim.x + threadIdx.x;
    if (i >= N_NODES) return;
    float dv = g_dinv[i];
    float d2 = dv * dv;
    float4* a  = reinterpret_cast<float4*>(g_agg1 + (size_t)i * HID);
    const float4* h = reinterpret_cast<const float4*>(g_h1 + (size_t)i * HID);
    const float4* bb = reinterpret_cast<const float4*>(b1);
    #pragma unroll
    for (int q = 0; q < 4; q++) {
        float4 av = a[q];
        float4 hv = h[q];
        float4 bv = __ldg(&bb[q]);
        av.x = fmaxf(av.x + d2 * hv.x + bv.x, 0.0f);
        av.y = fmaxf(av.y + d2 * hv.y + bv.y, 0.0f);
        av.z = fmaxf(av.z + d2 * hv.z + bv.z, 0.0f);
        av.w = fmaxf(av.w + d2 * hv.w + bv.w, 0.0f);
        a[q] = av;
    }
}

// ---------------- GEMM2: h2 = relu_h @ W2   (100000 x 16 x 7, padded to 8) ----------------
__global__ void k_gemm2(const float* __restrict__ W2) {
    __shared__ float Ws[HID * CLS];
    if (threadIdx.x < HID * CLS) Ws[threadIdx.x] = W2[threadIdx.x];
    __syncthreads();

    int i = blockIdx.x * blockDim.x + threadIdx.x;
    if (i >= N_NODES) return;

    float acc[CLS];
    #pragma unroll
    for (int j = 0; j < CLS; j++) acc[j] = 0.0f;

    const float4* hr = reinterpret_cast<const float4*>(g_agg1 + (size_t)i * HID);
    #pragma unroll
    for (int q = 0; q < 4; q++) {
        float4 v = hr[q];
        int k = q * 4;
        #pragma unroll
        for (int j = 0; j < CLS; j++) acc[j] = fmaf(v.x, Ws[(k + 0) * CLS + j], acc[j]);
        #pragma unroll
        for (int j = 0; j < CLS; j++) acc[j] = fmaf(v.y, Ws[(k + 1) * CLS + j], acc[j]);
        #pragma unroll
        for (int j = 0; j < CLS; j++) acc[j] = fmaf(v.z, Ws[(k + 2) * CLS + j], acc[j]);
        #pragma unroll
        for (int j = 0; j < CLS; j++) acc[j] = fmaf(v.w, Ws[(k + 3) * CLS + j], acc[j]);
    }
    float* o = g_h2 + (size_t)i * HID2;
    #pragma unroll
    for (int j = 0; j < CLS; j++) o[j] = acc[j];
    o[CLS] = 0.0f;   // pad
}

// ---------------- edge scatter, layer 2 ----------------
__global__ void k_edge2(const void* __restrict__ ei, int E) {
    int i = blockIdx.x * blockDim.x + threadIdx.x;
    if (i >= E) return;
    int src, dst;
    if (g_is64) {
        const long long* e = (const long long*)ei;
        src = (int)__ldg(&e[i]); dst = (int)__ldg(&e[(size_t)E + i]);
    } else {
        const int* e = (const int*)ei;
        src = __ldg(&e[i]); dst = __ldg(&e[(size_t)E + i]);
    }
    float wgt = __ldg(&g_dinv[src]) * __ldg(&g_dinv[dst]);
    const float4* hs = reinterpret_cast<const float4*>(g_h2 + (size_t)src * HID2);
    float* ad = g_agg2 + (size_t)dst * HID2;
    #pragma unroll
    for (int q = 0; q < 2; q++) {
        float4 v = __ldg(&hs[q]);
        red_add_v4(ad + q * 4, v.x * wgt, v.y * wgt, v.z * wgt, v.w * wgt);
    }
}

// ---------------- finalize2: self loop + bias -> d_out ----------------
__global__ void k_fin2(const float* __restrict__ b2, float* __restrict__ out) {
    int i = blockIdx.x * blockDim.x + threadIdx.x;
    if (i >= N_NODES) return;
    float dv = g_dinv[i];
    float d2 = dv * dv;
    const float* a = g_agg2 + (size_t)i * HID2;
    const float* h = g_h2   + (size_t)i * HID2;
    float* o = out + (size_t)i * CLS;
    #pragma unroll
    for (int j = 0; j < CLS; j++)
        o[j] = a[j] + d2 * h[j] + __ldg(&b2[j]);
}

// ---------------- launch ----------------
extern "C" void kernel_launch(void* const* d_in, const int* in_sizes, int n_in,
                              void* d_out, int out_size) {
    const float* x  = (const float*)d_in[0];
    const void*  ei = d_in[1];
    const float* W1 = (const float*)d_in[2];
    const float* b1 = (const float*)d_in[3];
    const float* W2 = (const float*)d_in[4];
    const float* b2 = (const float*)d_in[5];
    float* out = (float*)d_out;

    int E = in_sizes[1] / 2;

    const int TPB = 256;
    int nb_nodes = (N_NODES + TPB - 1) / TPB;
    int nb_edges = (E + TPB - 1) / TPB;

    k_detect<<<1, 32>>>((const unsigned int*)ei);
    k_init<<<512, TPB>>>();
    k_deg<<<nb_edges, TPB>>>(ei, E);
    k_dinv<<<nb_nodes, TPB>>>();
    k_gemm1<<<nb_nodes, TPB>>>(x, W1);
    k_edge1<<<nb_edges, TPB>>>(ei, E);
    k_fin1<<<nb_nodes, TPB>>>(b1);
    k_gemm2<<<nb_nodes, TPB>>>(W2);
    k_edge2<<<nb_edges, TPB>>>(ei, E);
    k_fin2<<<nb_nodes, TPB>>>(b2, out);
}